// round 3
// baseline (speedup 1.0000x reference)
#include <cuda_runtime.h>
#include <cuda_bf16.h>

#define B 128
#define S 256
#define C 64

// Per-batch (free_energy - path_energy); reduced by crf_reduce.
__device__ float g_scratch[B];

__global__ __launch_bounds__(128, 1) void crf_main(
    const float* __restrict__ emis,   // [B, S, C]
    const int*   __restrict__ tags,   // [B, S]
    const float* __restrict__ mask,   // [B, S]
    const float* __restrict__ U)      // [C, C]
{
    const int b    = blockIdx.x;
    const int tid  = threadIdx.x;
    const int w    = tid >> 5;          // warp 0..3
    const int lane = tid & 31;
    const int j    = w * 16 + (lane >> 1);  // column owned (pair of lanes per column)
    const int h    = lane & 1;              // i-half: h=0 -> i in [0,32), h=1 -> [32,64)

    __shared__ __align__(16) float sh_e[2][C];  // double-buffered normalized alpha (linear space)
    __shared__ float sh_red[128];               // path-energy partials

    const float* embase = emis + (size_t)b * S * C;
    const float* mbase  = mask + b * S;
    const int*   tbase  = tags + b * S;

    // ---------------- path energy partials (2 timesteps per thread) ----------------
    float pp = 0.f;
#pragma unroll
    for (int q = 0; q < 2; ++q) {
        int   s  = 2 * tid + q;
        int   tg = tbase[s];
        float m  = mbase[s];
        int   tm = (int)((float)tg * m);          // matches (tags*mask).astype(int32)
        pp += embase[s * C + tm] * m;
        if (s >= 1) {
            int tp = tbase[s - 1];
            pp += U[tp * C + tg] * m;             // raw tags for transition term
        }
    }
    sh_red[tid] = pp;

    // ---------------- exp(U) slice into registers: my i-half for my column ----------------
    float uexp[32];
#pragma unroll
    for (int k = 0; k < 32; ++k)
        uexp[k] = __expf(U[(h * 32 + k) * C + j]);

    // ---------------- init: e = exp(alpha_0) ----------------
    if (h == 0)
        sh_e[0][j] = __expf(embase[j]);
    __syncthreads();

    float base = 0.f;   // cumulative log-shift (valid on h==0 lanes)
    int   cur  = 0;

    // emission prefetch pipeline (distance 4); exp(em) hoisted off the serial chain
    float eem0 = __expf(embase[1 * C + j]), eem1 = __expf(embase[2 * C + j]);
    float eem2 = __expf(embase[3 * C + j]), eem3 = __expf(embase[4 * C + j]);
    float m0 = mbase[1], m1 = mbase[2], m2 = mbase[3], m3 = mbase[4];

    auto step = [&](float eem_t, float m_t) {
        const float4* ev = (const float4*)(&sh_e[cur][h * 32]);
        float4 f0  = ev[0];
        float  e0v = f0.x;                       // e[0] on h==0 lanes (the normalizer)
        float  r0c = __fdividef(1.f, e0v);       // issued early; latency hides under FMA tree
        float s0, s1, s2, s3;
        if (m_t != 0.f) {
            s0 = f0.x * uexp[0]; s1 = f0.y * uexp[1];
            s2 = f0.z * uexp[2]; s3 = f0.w * uexp[3];
#pragma unroll
            for (int q = 1; q < 8; ++q) {
                float4 e4 = ev[q];
                s0 = fmaf(e4.x, uexp[4 * q + 0], s0);
                s1 = fmaf(e4.y, uexp[4 * q + 1], s1);
                s2 = fmaf(e4.z, uexp[4 * q + 2], s2);
                s3 = fmaf(e4.w, uexp[4 * q + 3], s3);
            }
        } else {
            // masked step: alpha_new_j = logsumexp_i(alpha_i) for all j
            s0 = f0.x; s1 = f0.y; s2 = f0.z; s3 = f0.w;
#pragma unroll
            for (int q = 1; q < 8; ++q) {
                float4 e4 = ev[q];
                s0 += e4.x; s1 += e4.y; s2 += e4.z; s3 += e4.w;
            }
        }
        float part  = (s0 + s1) + (s2 + s3);
        float other = __shfl_xor_sync(0xFFFFFFFFu, part, 1);
        if (!h) {
            float ssum  = part + other;
            base += __logf(e0v);
            float scale = (m_t != 0.f) ? eem_t * r0c : r0c;
            sh_e[cur ^ 1][j] = ssum * scale;     // e_new = s * exp(em) / e0
        }
        __syncthreads();                          // single barrier per step
        cur ^= 1;
    };

    // t = 1 .. 252 in groups of 4 (prefetch 4 ahead), then 253..255 tail
    for (int t0 = 1; t0 + 3 < S; t0 += 4) {
        step(eem0, m0);
        if (t0 + 4 < S) { eem0 = __expf(embase[(t0 + 4) * C + j]); m0 = mbase[t0 + 4]; }
        step(eem1, m1);
        if (t0 + 5 < S) { eem1 = __expf(embase[(t0 + 5) * C + j]); m1 = mbase[t0 + 5]; }
        step(eem2, m2);
        if (t0 + 6 < S) { eem2 = __expf(embase[(t0 + 6) * C + j]); m2 = mbase[t0 + 6]; }
        step(eem3, m3);
        if (t0 + 7 < S) { eem3 = __expf(embase[(t0 + 7) * C + j]); m3 = mbase[t0 + 7]; }
    }
    step(eem0, m0);   // t = 253
    step(eem1, m1);   // t = 254
    step(eem2, m2);   // t = 255

    // ---------------- finalize: free = log(sum_j e_j) + base ----------------
    // base lives on the thread owning column 0, h==0 -> warp 0 lane 0 == tid 0
    if (tid == 0) {
        float sE = 0.f;
#pragma unroll
        for (int k = 0; k < C; ++k) sE += sh_e[cur][k];
        float freeE = __logf(sE) + base;
        float pathE = 0.f;
#pragma unroll
        for (int k = 0; k < 128; ++k) pathE += sh_red[k];
        g_scratch[b] = freeE - pathE;
    }
}

__global__ __launch_bounds__(128, 1) void crf_reduce(float* __restrict__ out)
{
    const int tid  = threadIdx.x;
    const int lane = tid & 31;
    const int w    = tid >> 5;
    __shared__ float sh[4];

    float v = g_scratch[tid];
#pragma unroll
    for (int o = 16; o > 0; o >>= 1)
        v += __shfl_xor_sync(0xFFFFFFFFu, v, o);
    if (lane == 0) sh[w] = v;
    __syncthreads();
    if (tid == 0)
        out[0] = (sh[0] + sh[1] + sh[2] + sh[3]) * (1.f / (float)B);
}

extern "C" void kernel_launch(void* const* d_in, const int* in_sizes, int n_in,
                              void* d_out, int out_size)
{
    const float* emis = (const float*)d_in[0];
    const int*   tags = (const int*)d_in[1];
    const float* mask = (const float*)d_in[2];
    const float* U    = (const float*)d_in[3];

    crf_main<<<B, 128>>>(emis, tags, mask, U);
    crf_reduce<<<1, 128>>>((float*)d_out);
}

// round 4
// speedup vs baseline: 1.1610x; 1.1610x over previous
#include <cuda_runtime.h>
#include <cuda_bf16.h>

#define B 128
#define S 256
#define C 64

__device__ float g_scratch[B];
__device__ int   g_count = 0;

// ---- packed f32x2 helpers (sm_100+; ptxas won't auto-fuse these) ----
__device__ __forceinline__ unsigned long long f2_mul(unsigned long long a, unsigned long long b) {
    unsigned long long d;
    asm("mul.rn.f32x2 %0, %1, %2;" : "=l"(d) : "l"(a), "l"(b));
    return d;
}
__device__ __forceinline__ unsigned long long f2_fma(unsigned long long a, unsigned long long b, unsigned long long c) {
    unsigned long long d;
    asm("fma.rn.f32x2 %0, %1, %2, %3;" : "=l"(d) : "l"(a), "l"(b), "l"(c));
    return d;
}
__device__ __forceinline__ unsigned long long f2_add(unsigned long long a, unsigned long long b) {
    unsigned long long d;
    asm("add.rn.f32x2 %0, %1, %2;" : "=l"(d) : "l"(a), "l"(b));
    return d;
}
__device__ __forceinline__ float f2_hsum(unsigned long long p) {
    unsigned lo, hi;
    asm("mov.b64 {%0,%1}, %2;" : "=r"(lo), "=r"(hi) : "l"(p));
    return __uint_as_float(lo) + __uint_as_float(hi);
}
__device__ __forceinline__ unsigned long long f2_pack(float x, float y) {
    unsigned long long d;
    asm("mov.b64 %0, {%1,%2};" : "=l"(d) : "f"(x), "f"(y));
    return d;
}

__global__ __launch_bounds__(64, 1) void crf_main(
    const float* __restrict__ emis,   // [B, S, C]
    const int*   __restrict__ tags,   // [B, S]
    const float* __restrict__ mask,   // [B, S]
    const float* __restrict__ U,      // [C, C]
    float*       __restrict__ out)
{
    const int b = blockIdx.x;
    const int j = threadIdx.x;        // 0..63: column owned (full dot product)
    const int lane = j & 31;
    const int w    = j >> 5;

    __shared__ __align__(16) float sh_e[2][C];  // double-buffered normalized alpha (linear)
    __shared__ float sh_s[2], sh_r[2];
    __shared__ int   sh_last;

    const float* embase = emis + (size_t)b * S * C;
    const float* mbase  = mask + b * S;
    const int*   tbase  = tags + b * S;

    // ---------------- path energy partials (4 timesteps per thread) ----------------
    float pp = 0.f;
#pragma unroll
    for (int q = 0; q < 4; ++q) {
        int   s  = 4 * j + q;
        int   tg = tbase[s];
        float m  = mbase[s];
        int   tm = (int)((float)tg * m);          // matches (tags*mask).astype(int32)
        pp += embase[s * C + tm] * m;
        if (s >= 1) {
            int tp = tbase[s - 1];
            pp += U[tp * C + tg] * m;             // raw tags for transition term
        }
    }

    // ---------------- exp(U) column j, packed as 32 f32x2 pairs ----------------
    unsigned long long u2[32];
#pragma unroll
    for (int k = 0; k < 32; ++k)
        u2[k] = f2_pack(__expf(U[(2 * k) * C + j]),
                        __expf(U[(2 * k + 1) * C + j]));

    // ---------------- init: e = exp(alpha_0) ----------------
    sh_e[0][j] = __expf(embase[j]);
    __syncthreads();

    float base = 0.f;   // cumulative log-shift (identical on all threads; uniform work)
    int   cur  = 0;

    // emission prefetch pipeline (distance 4); exp(em) off the serial chain
    float eem0 = __expf(embase[1 * C + j]), eem1 = __expf(embase[2 * C + j]);
    float eem2 = __expf(embase[3 * C + j]), eem3 = __expf(embase[4 * C + j]);
    float m0 = mbase[1], m1 = mbase[2], m2 = mbase[3], m3 = mbase[4];

    auto step = [&](float eem_t, float m_t) {
        const ulonglong2* ev = (const ulonglong2*)(&sh_e[cur][0]);  // 16B-aligned pairs
        float e0v = sh_e[cur][0];                 // normalizer (broadcast LDS)
        float r0c = __fdividef(1.f, e0v);         // MUFU latency hides under FMA tree
        base += __logf(e0v);                      // uniform on all threads: no branch
        float part, scale;
        if (m_t != 0.f) {                         // block-uniform branch
            ulonglong2 v0 = ev[0], v1 = ev[1];
            unsigned long long a0 = f2_mul(v0.x, u2[0]);
            unsigned long long a1 = f2_mul(v0.y, u2[1]);
            unsigned long long a2 = f2_mul(v1.x, u2[2]);
            unsigned long long a3 = f2_mul(v1.y, u2[3]);
#pragma unroll
            for (int q = 2; q < 16; q += 2) {
                ulonglong2 va = ev[q], vb = ev[q + 1];
                a0 = f2_fma(va.x, u2[2 * q + 0], a0);
                a1 = f2_fma(va.y, u2[2 * q + 1], a1);
                a2 = f2_fma(vb.x, u2[2 * q + 2], a2);
                a3 = f2_fma(vb.y, u2[2 * q + 3], a3);
            }
            part  = f2_hsum(f2_add(f2_add(a0, a1), f2_add(a2, a3)));
            scale = eem_t * r0c;
        } else {
            // masked step: alpha_new_j = logsumexp_i(alpha_i) for all j
            float ssum = 0.f;
#pragma unroll
            for (int i = 0; i < C; ++i) ssum += sh_e[cur][i];
            part  = ssum;
            scale = r0c;
        }
        sh_e[cur ^ 1][j] = part * scale;          // e_new = s * exp(em) / e0
        __syncthreads();                           // single barrier per step (2 warps)
        cur ^= 1;
    };

    // t = 1 .. 252 in groups of 4 (prefetch 4 ahead), then 253..255 tail
    for (int t0 = 1; t0 + 3 < S; t0 += 4) {
        step(eem0, m0);
        if (t0 + 4 < S) { eem0 = __expf(embase[(t0 + 4) * C + j]); m0 = mbase[t0 + 4]; }
        step(eem1, m1);
        if (t0 + 5 < S) { eem1 = __expf(embase[(t0 + 5) * C + j]); m1 = mbase[t0 + 5]; }
        step(eem2, m2);
        if (t0 + 6 < S) { eem2 = __expf(embase[(t0 + 6) * C + j]); m2 = mbase[t0 + 6]; }
        step(eem3, m3);
        if (t0 + 7 < S) { eem3 = __expf(embase[(t0 + 7) * C + j]); m3 = mbase[t0 + 7]; }
    }
    step(eem0, m0);   // t = 253
    step(eem1, m1);   // t = 254
    step(eem2, m2);   // t = 255

    // ---------------- finalize: parallel reductions of e-sum and path energy ----------------
    float fv = sh_e[cur][j];
#pragma unroll
    for (int o = 16; o > 0; o >>= 1) {
        fv += __shfl_xor_sync(0xFFFFFFFFu, fv, o);
        pp += __shfl_xor_sync(0xFFFFFFFFu, pp, o);
    }
    if (lane == 0) { sh_s[w] = fv; sh_r[w] = pp; }
    __syncthreads();

    if (j == 0) {
        float freeE = __logf(sh_s[0] + sh_s[1]) + base;
        float pathE = sh_r[0] + sh_r[1];
        g_scratch[b] = freeE - pathE;
        __threadfence();
        sh_last = (atomicAdd(&g_count, 1) == B - 1) ? 1 : 0;
    }
    __syncthreads();

    // ---------------- last block: reduce all batches, write mean, reset counter ----------------
    if (sh_last) {
        float v = g_scratch[2 * j] + g_scratch[2 * j + 1];   // 64 threads cover 128 batches
#pragma unroll
        for (int o = 16; o > 0; o >>= 1)
            v += __shfl_xor_sync(0xFFFFFFFFu, v, o);
        if (lane == 0) sh_s[w] = v;
        __syncthreads();
        if (j == 0) {
            out[0] = (sh_s[0] + sh_s[1]) * (1.f / (float)B);
            g_count = 0;                                     // replay-safe reset
        }
    }
}

extern "C" void kernel_launch(void* const* d_in, const int* in_sizes, int n_in,
                              void* d_out, int out_size)
{
    const float* emis = (const float*)d_in[0];
    const int*   tags = (const int*)d_in[1];
    const float* mask = (const float*)d_in[2];
    const float* U    = (const float*)d_in[3];

    crf_main<<<B, 64>>>(emis, tags, mask, U, (float*)d_out);
}

// round 5
// speedup vs baseline: 1.2879x; 1.1093x over previous
#include <cuda_runtime.h>
#include <cuda_bf16.h>

#define B 128
#define S 256
#define C 64

__device__ float g_scratch[B];
__device__ int   g_count = 0;

// ---- packed f32x2 helpers (sm_100+) ----
__device__ __forceinline__ unsigned long long f2_mul(unsigned long long a, unsigned long long b) {
    unsigned long long d;
    asm("mul.rn.f32x2 %0, %1, %2;" : "=l"(d) : "l"(a), "l"(b));
    return d;
}
__device__ __forceinline__ unsigned long long f2_fma(unsigned long long a, unsigned long long b, unsigned long long c) {
    unsigned long long d;
    asm("fma.rn.f32x2 %0, %1, %2, %3;" : "=l"(d) : "l"(a), "l"(b), "l"(c));
    return d;
}
__device__ __forceinline__ unsigned long long f2_add(unsigned long long a, unsigned long long b) {
    unsigned long long d;
    asm("add.rn.f32x2 %0, %1, %2;" : "=l"(d) : "l"(a), "l"(b));
    return d;
}
__device__ __forceinline__ float f2_hsum(unsigned long long p) {
    unsigned lo, hi;
    asm("mov.b64 {%0,%1}, %2;" : "=r"(lo), "=r"(hi) : "l"(p));
    return __uint_as_float(lo) + __uint_as_float(hi);
}
__device__ __forceinline__ unsigned long long f2_pack(float x, float y) {
    unsigned long long d;
    asm("mov.b64 %0, {%1,%2};" : "=l"(d) : "f"(x), "f"(y));
    return d;
}

__global__ __launch_bounds__(256, 1) void crf_main(
    const float* __restrict__ emis,   // [B, S, C]
    const int*   __restrict__ tags,   // [B, S]
    const float* __restrict__ mask,   // [B, S]
    const float* __restrict__ U,      // [C, C]
    float*       __restrict__ out)
{
    const int b    = blockIdx.x;
    const int tid  = threadIdx.x;
    const int j    = tid & 63;        // column owned
    const int h    = tid >> 6;        // i-quarter 0..3 (warp-uniform: warps 2h, 2h+1)
    const int lane = tid & 31;
    const int w    = tid >> 5;

    __shared__ __align__(16) float sh_e[2][C];   // double-buffered normalized alpha (linear)
    __shared__ __align__(16) float sh_p[4][C];   // per-quarter scaled partials
    __shared__ float sh_r[8], sh_s[2];
    __shared__ int   sh_last;

    const float* embase = emis + (size_t)b * S * C;
    const float* mbase  = mask + b * S;
    const int*   tbase  = tags + b * S;

    // ---------------- path energy partial (1 timestep per thread) ----------------
    float pp;
    {
        int   s  = tid;
        int   tg = tbase[s];
        float m  = mbase[s];
        int   tm = (int)((float)tg * m);          // matches (tags*mask).astype(int32)
        pp = embase[s * C + tm] * m;
        if (s >= 1) {
            int tp = tbase[s - 1];
            pp += U[tp * C + tg] * m;             // raw tags for transition term
        }
    }

    // ---------------- exp(U) quarter-slice for column j: 8 packed pairs ----------------
    unsigned long long u2[8];
#pragma unroll
    for (int k = 0; k < 8; ++k)
        u2[k] = f2_pack(__expf(U[(h * 16 + 2 * k)     * C + j]),
                        __expf(U[(h * 16 + 2 * k + 1) * C + j]));

    // ---------------- init: e = exp(alpha_0) ----------------
    if (h == 0)
        sh_e[0][j] = __expf(embase[j]);
    __syncthreads();

    float base = 0.f;   // cumulative log-shift (uniform on all threads)
    int   cur  = 0;

    // emission prefetch pipeline (distance 4); exp(em) off the serial chain
    float eem0 = __expf(embase[1 * C + j]), eem1 = __expf(embase[2 * C + j]);
    float eem2 = __expf(embase[3 * C + j]), eem3 = __expf(embase[4 * C + j]);
    float m0 = mbase[1], m1 = mbase[2], m2 = mbase[3], m3 = mbase[4];

    auto step = [&](float eem_t, float m_t) {
        const ulonglong2* ev = (const ulonglong2*)(&sh_e[cur][h * 16]);  // 16 floats = 4x16B
        float e0v = sh_e[cur][0];                 // broadcast LDS
        float r0c = __fdividef(1.f, e0v);         // MUFU hides under FMA tree
        base += __logf(e0v);                      // uniform, off-chain
        float part, scale;
        if (m_t != 0.f) {                         // block-uniform branch
            ulonglong2 va = ev[0], vb = ev[1];
            unsigned long long a0 = f2_mul(va.x, u2[0]);
            unsigned long long a1 = f2_mul(va.y, u2[1]);
            a0 = f2_fma(vb.x, u2[2], a0);
            a1 = f2_fma(vb.y, u2[3], a1);
            va = ev[2]; vb = ev[3];
            a0 = f2_fma(va.x, u2[4], a0);
            a1 = f2_fma(va.y, u2[5], a1);
            a0 = f2_fma(vb.x, u2[6], a0);
            a1 = f2_fma(vb.y, u2[7], a1);
            part  = f2_hsum(f2_add(a0, a1));
            scale = eem_t * r0c;
        } else {
            // masked step: alpha_new_j = logsumexp_i(alpha_i)
            float ssum = 0.f;
#pragma unroll
            for (int i = 0; i < 16; ++i) ssum += sh_e[cur][h * 16 + i];
            part  = ssum;
            scale = r0c;
        }
        sh_p[h][j] = part * scale;                // scale folded per-partial
        __syncthreads();                           // barA
        if (h == 0) {                              // warps 0,1: pure-add combine
            sh_e[cur ^ 1][j] = (sh_p[0][j] + sh_p[1][j]) + (sh_p[2][j] + sh_p[3][j]);
        }
        __syncthreads();                           // barB
        cur ^= 1;
    };

    // t = 1 .. 252 in groups of 4 (prefetch 4 ahead), then 253..255 tail
    for (int t0 = 1; t0 + 3 < S; t0 += 4) {
        step(eem0, m0);
        if (t0 + 4 < S) { eem0 = __expf(embase[(t0 + 4) * C + j]); m0 = mbase[t0 + 4]; }
        step(eem1, m1);
        if (t0 + 5 < S) { eem1 = __expf(embase[(t0 + 5) * C + j]); m1 = mbase[t0 + 5]; }
        step(eem2, m2);
        if (t0 + 6 < S) { eem2 = __expf(embase[(t0 + 6) * C + j]); m2 = mbase[t0 + 6]; }
        step(eem3, m3);
        if (t0 + 7 < S) { eem3 = __expf(embase[(t0 + 7) * C + j]); m3 = mbase[t0 + 7]; }
    }
    step(eem0, m0);   // t = 253
    step(eem1, m1);   // t = 254
    step(eem2, m2);   // t = 255

    // ---------------- finalize: free = log(sum_j e_j) + base ; path = sum pp ----------------
    float fv = (tid < C) ? sh_e[cur][tid] : 0.f;
#pragma unroll
    for (int o = 16; o > 0; o >>= 1) {
        fv += __shfl_xor_sync(0xFFFFFFFFu, fv, o);
        pp += __shfl_xor_sync(0xFFFFFFFFu, pp, o);
    }
    if (lane == 0) { sh_r[w] = pp; if (w < 2) sh_s[w] = fv; }
    __syncthreads();

    if (tid == 0) {
        float freeE = __logf(sh_s[0] + sh_s[1]) + base;
        float pathE = 0.f;
#pragma unroll
        for (int k = 0; k < 8; ++k) pathE += sh_r[k];
        g_scratch[b] = freeE - pathE;
        __threadfence();
        sh_last = (atomicAdd(&g_count, 1) == B - 1) ? 1 : 0;
    }
    __syncthreads();

    // ---------------- last block: reduce all batches, write mean, reset counter ----------------
    if (sh_last) {
        float v = (tid < B) ? g_scratch[tid] : 0.f;
#pragma unroll
        for (int o = 16; o > 0; o >>= 1)
            v += __shfl_xor_sync(0xFFFFFFFFu, v, o);
        if (lane == 0) sh_r[w] = v;
        __syncthreads();
        if (tid == 0) {
            float s = 0.f;
#pragma unroll
            for (int k = 0; k < 8; ++k) s += sh_r[k];
            out[0] = s * (1.f / (float)B);
            g_count = 0;                           // replay-safe reset
        }
    }
}

extern "C" void kernel_launch(void* const* d_in, const int* in_sizes, int n_in,
                              void* d_out, int out_size)
{
    const float* emis = (const float*)d_in[0];
    const int*   tags = (const int*)d_in[1];
    const float* mask = (const float*)d_in[2];
    const float* U    = (const float*)d_in[3];

    crf_main<<<B, 256>>>(emis, tags, mask, U, (float*)d_out);
}

// round 6
// speedup vs baseline: 1.8874x; 1.4655x over previous
#include <cuda_runtime.h>
#include <cuda_bf16.h>

#define B 128
#define S 256
#define C 64

__device__ float g_scratch[B];
__device__ int   g_count = 0;

__global__ __launch_bounds__(128, 1) void crf_main(
    const float* __restrict__ emis,   // [B, S, C]
    const int*   __restrict__ tags,   // [B, S]
    const float* __restrict__ mask,   // [B, S]
    const float* __restrict__ U,      // [C, C]
    float*       __restrict__ out)
{
    const int b   = blockIdx.x;
    const int tid = threadIdx.x;
    const int w   = tid >> 5;          // warp 0..3
    const int l   = tid & 31;
    // warp quadrants: (i-half a, j-half jh) = w0:(0,0) w1:(1,1) w2:(1,0) w3:(0,1)
    const int a   = ((w + 1) >> 1) & 1;
    const int jh  = w & 1;
    const int c   = a * 32 + l;        // column this lane rebuilds (= its read-slice element)
    const int jo  = jh * 32 + l;       // column this lane computes the partial for

    __shared__ __align__(16) float sh_E[4][32];     // per-warp private e-slice (i in a-half)
    __shared__ __align__(16) float sh_p[2][2][C];   // [buf][i-half][j] partials (double-buffered)
    __shared__ float sh_r[4], sh_s[2];
    __shared__ int   sh_last;

    const float* embase = emis + (size_t)b * S * C;
    const float* mbase  = mask + b * S;
    const int*   tbase  = tags + b * S;

    // ---------------- path energy partials (2 timesteps per thread) ----------------
    float pp = 0.f;
    int   ok = 1;
#pragma unroll
    for (int q = 0; q < 2; ++q) {
        int   s  = 2 * tid + q;
        int   tg = tbase[s];
        float m  = mbase[s];
        int   tm = (int)((float)tg * m);          // matches (tags*mask).astype(int32)
        pp += embase[s * C + tm] * m;
        if (s >= 1) {
            int tp = tbase[s - 1];
            pp += U[tp * C + tg] * m;             // raw tags for transition term
            ok &= (m == 1.f);                     // fast path requires mask[1:]==1
        }
    }
    const int allm = __syncthreads_and(ok);       // block-uniform flag (also a full bar)

    // ---------------- exp(U) quadrant: rows a-half, column jo ----------------
    float ue[32];
#pragma unroll
    for (int k = 0; k < 32; ++k)
        ue[k] = __expf(U[(a * 32 + k) * C + jo]);

    // ---------------- init: private e-slice = exp(alpha_0) on my i-half ----------------
    sh_E[w][l] = __expf(embase[c]);

    float base = 0.f;   // cumulative log-shift (uniform on all threads)
    int   pb   = 0;     // sh_p buffer parity

    if (allm) {
        // ---- fast loop: mask==1 everywhere, zero branches per step ----
        float e0 = __expf(embase[1 * C + c]), e1 = __expf(embase[2 * C + c]);
        float e2 = __expf(embase[3 * C + c]), e3 = __expf(embase[4 * C + c]);

        auto stepf = [&](float eem) {
            __syncwarp();                                   // order prior e-writes vs reads
            const float4* ev = (const float4*)sh_E[w];      // broadcast reads, conflict-free
            float4 v = ev[0];
            float a0 = v.x * ue[0], a1 = v.y * ue[1], a2 = v.z * ue[2], a3 = v.w * ue[3];
#pragma unroll
            for (int q = 1; q < 8; ++q) {
                float4 vq = ev[q];
                a0 = fmaf(vq.x, ue[4 * q + 0], a0);
                a1 = fmaf(vq.y, ue[4 * q + 1], a1);
                a2 = fmaf(vq.z, ue[4 * q + 2], a2);
                a3 = fmaf(vq.w, ue[4 * q + 3], a3);
            }
            sh_p[pb][a][jo] = (a0 + a1) + (a2 + a3);
            __syncthreads();                                // single block bar per step
            float s00 = sh_p[pb][0][0] + sh_p[pb][1][0];    // shared normalizer s_0
            float r   = __fdividef(1.f, s00);
            base += __logf(s00);
            float sc  = sh_p[pb][0][c] + sh_p[pb][1][c];
            sh_E[w][l] = sc * (eem * r);                    // rebuild own slice redundantly
            pb ^= 1;
        };

        for (int t0 = 1; t0 + 3 < S; t0 += 4) {             // t = 1..252
            stepf(e0); e0 = __expf(embase[min(t0 + 4, S - 1) * C + c]);
            stepf(e1); e1 = __expf(embase[min(t0 + 5, S - 1) * C + c]);
            stepf(e2); e2 = __expf(embase[min(t0 + 6, S - 1) * C + c]);
            stepf(e3); e3 = __expf(embase[min(t0 + 7, S - 1) * C + c]);
        }
        stepf(e0); stepf(e1); stepf(e2);                    // t = 253,254,255
    } else {
        // ---- general loop: per-step mask in {0,1} ----
        for (int t = 1; t < S; ++t) {
            float m   = mbase[t];
            float eem = __expf(embase[t * C + c]);
            __syncwarp();
            float part;
            if (m != 0.f) {
                const float4* ev = (const float4*)sh_E[w];
                float4 v = ev[0];
                float a0 = v.x * ue[0], a1 = v.y * ue[1], a2 = v.z * ue[2], a3 = v.w * ue[3];
#pragma unroll
                for (int q = 1; q < 8; ++q) {
                    float4 vq = ev[q];
                    a0 = fmaf(vq.x, ue[4 * q + 0], a0);
                    a1 = fmaf(vq.y, ue[4 * q + 1], a1);
                    a2 = fmaf(vq.z, ue[4 * q + 2], a2);
                    a3 = fmaf(vq.w, ue[4 * q + 3], a3);
                }
                part = (a0 + a1) + (a2 + a3);
            } else {
                float s = 0.f;                              // masked: plain sum of e_i
#pragma unroll
                for (int k = 0; k < 32; ++k) s += sh_E[w][k];
                part = s;
            }
            sh_p[pb][a][jo] = part;
            __syncthreads();
            float s00 = sh_p[pb][0][0] + sh_p[pb][1][0];
            float r   = __fdividef(1.f, s00);
            base += __logf(s00);
            float sc  = (m != 0.f) ? eem * r : r;
            sh_E[w][l] = (sh_p[pb][0][c] + sh_p[pb][1][c]) * sc;
            pb ^= 1;
        }
    }
    __syncthreads();

    // ---------------- finalize: free = log(sum_c e_c) + base ; path = sum pp ----------------
    float fv = (w < 2) ? sh_E[w][l] : 0.f;   // w0 holds c=0..31, w1 holds c=32..63
#pragma unroll
    for (int o = 16; o > 0; o >>= 1) {
        fv += __shfl_xor_sync(0xFFFFFFFFu, fv, o);
        pp += __shfl_xor_sync(0xFFFFFFFFu, pp, o);
    }
    if (l == 0) { sh_r[w] = pp; if (w < 2) sh_s[w] = fv; }
    __syncthreads();

    if (tid == 0) {
        float freeE = __logf(sh_s[0] + sh_s[1]) + base;
        float pathE = (sh_r[0] + sh_r[1]) + (sh_r[2] + sh_r[3]);
        g_scratch[b] = freeE - pathE;
        __threadfence();
        sh_last = (atomicAdd(&g_count, 1) == B - 1) ? 1 : 0;
    }
    __syncthreads();

    // ---------------- last block: reduce all batches, write mean, reset counter ----------------
    if (sh_last) {
        float v = g_scratch[tid];            // 128 threads cover B=128
#pragma unroll
        for (int o = 16; o > 0; o >>= 1)
            v += __shfl_xor_sync(0xFFFFFFFFu, v, o);
        if (l == 0) sh_r[w] = v;
        __syncthreads();
        if (tid == 0) {
            out[0] = ((sh_r[0] + sh_r[1]) + (sh_r[2] + sh_r[3])) * (1.f / (float)B);
            g_count = 0;                     // replay-safe reset
        }
    }
}

extern "C" void kernel_launch(void* const* d_in, const int* in_sizes, int n_in,
                              void* d_out, int out_size)
{
    const float* emis = (const float*)d_in[0];
    const int*   tags = (const int*)d_in[1];
    const float* mask = (const float*)d_in[2];
    const float* U    = (const float*)d_in[3];

    crf_main<<<B, 128>>>(emis, tags, mask, U, (float*)d_out);
}

// round 7
// speedup vs baseline: 2.2490x; 1.1916x over previous
#include <cuda_runtime.h>
#include <cuda_bf16.h>

#define B 128
#define S 256
#define C 64

__device__ float g_scratch[B];
__device__ int   g_count = 0;

__global__ __launch_bounds__(256, 1) void crf_main(
    const float* __restrict__ emis,   // [B, S, C]
    const int*   __restrict__ tags,   // [B, S]
    const float* __restrict__ mask,   // [B, S]
    const float* __restrict__ U,      // [C, C]
    float*       __restrict__ out)
{
    const int b   = blockIdx.x;
    const int tid = threadIdx.x;
    const int w   = tid >> 5;          // warp 0..7
    const int l   = tid & 31;
    const int qa  = w >> 1;            // i-quarter 0..3 (gather slice, 16 i-values)
    const int jh  = w & 1;             // j-half for partial computation
    const int jo  = jh * 32 + l;       // write-column (partial owner)
    const int c16 = qa * 16 + (l & 15);// rebuild-column (lanes 0..15 active)
    const bool lo16 = (l < 16);

    __shared__ __align__(16) float sh_E[8][16];      // per-warp private e-slice (i-quarter qa)
    __shared__ __align__(16) float sh_p[2][C][4];    // [buf][column][quarter], eem-scaled partials
    __shared__ float sh_r[8], sh_s[2];
    __shared__ int   sh_last;

    const float* embase = emis + (size_t)b * S * C;
    const float* mbase  = mask + b * S;
    const int*   tbase  = tags + b * S;

    // ---------------- path energy partial (1 timestep per thread) ----------------
    float pp;
    int   ok = 1;
    {
        int   s  = tid;
        int   tg = tbase[s];
        float m  = mbase[s];
        int   tm = (int)((float)tg * m);          // matches (tags*mask).astype(int32)
        pp = embase[s * C + tm] * m;
        if (s >= 1) {
            int tp = tbase[s - 1];
            pp += U[tp * C + tg] * m;             // raw tags for transition term
            ok &= (m == 1.f);
        }
    }
    const int allm = __syncthreads_and(ok);       // block-uniform fast-path flag

    // ---------------- exp(U) tile: rows in quarter qa, column jo (16 MACs) ----------------
    float ue[16];
#pragma unroll
    for (int k = 0; k < 16; ++k)
        ue[k] = __expf(U[(qa * 16 + k) * C + jo]);

    // ---------------- init: private e-slice = exp(alpha_0) on quarter qa ----------------
    if (lo16) sh_E[w][l & 15] = __expf(embase[c16]);

    float base = 0.f;     // cumulative log-shift (uniform)
    float rstale = 1.f;   // stale normalizer: 1/s00 of previous step (uniform)
    int   pb   = 0;

    if (allm) {
        // ======== fast loop: mask==1 everywhere ========
        // eem prefetch for write-column jo (folded into posted partial)
        float e0 = __expf(embase[1 * C + jo]), e1 = __expf(embase[2 * C + jo]);
        float e2 = __expf(embase[3 * C + jo]), e3 = __expf(embase[4 * C + jo]);

        auto stepf = [&](float eem) {
            __syncwarp();                                  // order e-writes vs gather reads
            const float4* ev = (const float4*)sh_E[w];     // 16 floats, broadcast
            float4 v = ev[0];
            float a0 = v.x * ue[0], a1 = v.y * ue[1], a2 = v.z * ue[2], a3 = v.w * ue[3];
            v = ev[1];
            a0 = fmaf(v.x, ue[4], a0);  a1 = fmaf(v.y, ue[5], a1);
            a2 = fmaf(v.z, ue[6], a2);  a3 = fmaf(v.w, ue[7], a3);
            v = ev[2];
            a0 = fmaf(v.x, ue[8], a0);  a1 = fmaf(v.y, ue[9], a1);
            a2 = fmaf(v.z, ue[10], a2); a3 = fmaf(v.w, ue[11], a3);
            v = ev[3];
            a0 = fmaf(v.x, ue[12], a0); a1 = fmaf(v.y, ue[13], a1);
            a2 = fmaf(v.z, ue[14], a2); a3 = fmaf(v.w, ue[15], a3);
            float part = ((a0 + a1) + (a2 + a3)) * eem;    // eem folded pre-bar
            sh_p[pb][jo][qa] = part;
            __syncthreads();                               // ONE block bar per step
            // uniform (off-chain next step): stale normalizer update
            float4 p0 = *(const float4*)sh_p[pb][0];
            float  s00 = (p0.x + p0.y) + (p0.z + p0.w);    // includes eem_0: fine, any shift works
            // on-chain combine: one LDS.128 + adds + mul + STS (lanes 0..15)
            if (lo16) {
                float4 pc = *(const float4*)sh_p[pb][c16];
                sh_E[w][l & 15] = ((pc.x + pc.y) + (pc.z + pc.w)) * rstale;
            }
            base  += __logf(s00) ;                          // shift applied NEXT step
            rstale = __fdividef(1.f, s00);
            pb ^= 1;
        };

        for (int t0 = 1; t0 + 3 < S; t0 += 4) {            // t = 1..252
            stepf(e0); e0 = __expf(embase[min(t0 + 4, S - 1) * C + jo]);
            stepf(e1); e1 = __expf(embase[min(t0 + 5, S - 1) * C + jo]);
            stepf(e2); e2 = __expf(embase[min(t0 + 6, S - 1) * C + jo]);
            stepf(e3); e3 = __expf(embase[min(t0 + 7, S - 1) * C + jo]);
        }
        stepf(e0); stepf(e1); stepf(e2);                   // t = 253,254,255
        // base/rstale bookkeeping: after the LAST step, base includes log(s00_last)
        // and the final e-slices were scaled by rstale of the prior step. The stored
        // vector is e_true * exp(-(base - log(s00_last))) ... handled below uniformly.
    } else {
        // ======== general loop: per-step mask in {0,1}, exact per-step normalization ========
        for (int t = 1; t < S; ++t) {
            float m   = mbase[t];
            float eem = __expf(embase[t * C + jo]);
            __syncwarp();
            float part;
            if (m != 0.f) {
                const float4* ev = (const float4*)sh_E[w];
                float4 v = ev[0];
                float a0 = v.x * ue[0], a1 = v.y * ue[1], a2 = v.z * ue[2], a3 = v.w * ue[3];
#pragma unroll
                for (int q = 1; q < 4; ++q) {
                    float4 vq = ev[q];
                    a0 = fmaf(vq.x, ue[4 * q + 0], a0);
                    a1 = fmaf(vq.y, ue[4 * q + 1], a1);
                    a2 = fmaf(vq.z, ue[4 * q + 2], a2);
                    a3 = fmaf(vq.w, ue[4 * q + 3], a3);
                }
                part = ((a0 + a1) + (a2 + a3)) * eem;
            } else {
                float s = 0.f;                             // masked: alpha_new_j = logsumexp_i(alpha_i)
#pragma unroll
                for (int k = 0; k < 16; ++k) s += sh_E[w][k];
                part = s;                                  // no eem on masked steps
            }
            sh_p[pb][jo][qa] = part;
            __syncthreads();
            float4 p0 = *(const float4*)sh_p[pb][0];
            float  s00 = (p0.x + p0.y) + (p0.z + p0.w);
            if (lo16) {
                float4 pc = *(const float4*)sh_p[pb][c16];
                sh_E[w][l & 15] = ((pc.x + pc.y) + (pc.z + pc.w)) * rstale;
            }
            base  += __logf(s00);
            rstale = __fdividef(1.f, s00);
            pb ^= 1;
        }
    }
    __syncthreads();

    // ---------------- finalize ----------------
    // Stored e-slices carry shift: stored = true * exp(-(base_applied)), where
    // base_applied = base - log(s00_last) (the last rstale was never applied to a
    // stored vector... careful): after final step, sh_E = (partials_last)*rstale_prev,
    // i.e. stored = s_last * rstale_prev; and base = sum over t=1..255 of log(s00_t).
    // true alpha sum: log(sum_j s_last_j) + sum_{t<255} log(s00_t)
    //              = log(sum_j stored_j) - log(rstale_prev) + (base - log(s00_255))
    //              = log(sum_j stored_j) + base - log(s00_255)   [rstale_prev = 1/s00_254... ]
    // To avoid index bookkeeping, recompute directly: stored_j = s_last_j * r_used where
    // r_used = 1/s00_{254}; base = Σ_{t=1..255} log s00_t. Then
    // log Σ s_last = log Σ stored - log r_used = log Σ stored + log s00_{254}.
    // free = log Σ s_last + Σ_{t=1..254} log s00_t = log Σ stored + Σ_{t=1..254} log s00 + log s00_254
    // Hmm — cleanest: track base only when a shift is APPLIED. Redo algebra numerically:
    // maintain invariant: stored(t) = true(t) * K(t), K(t) = K(t-1) * rstale_applied(t).
    // we applied rstale(t) = 1/s00(t-1) at step t (for t>=2; r=1 at t=1).
    // so K(255) = prod_{t=2..255} 1/s00(t-1) = prod_{u=1..254} 1/s00(u).
    // free = log( Σ stored / K ) = log Σ stored + Σ_{u=1..254} log s00(u) = log Σ stored + base - log s00(255).
    // base above accumulated t=1..255 inclusive, so subtract the last term:
    // (we saved the last s00 in rstale: rstale = 1/s00_last)
    float corr = __logf(rstale);                    // = -log s00_last
    float fv = 0.f;
    if (tid < C) {                                   // read e from jh=0 warps' slices
        int qq = tid >> 4;
        fv = sh_E[2 * qq][tid & 15];
    }
#pragma unroll
    for (int o = 16; o > 0; o >>= 1) {
        fv += __shfl_xor_sync(0xFFFFFFFFu, fv, o);
        pp += __shfl_xor_sync(0xFFFFFFFFu, pp, o);
    }
    if (l == 0) { sh_r[w] = pp; if (w < 2) sh_s[w] = fv; }
    __syncthreads();

    if (tid == 0) {
        float freeE = __logf(sh_s[0] + sh_s[1]) + base + corr;
        float pathE = 0.f;
#pragma unroll
        for (int k = 0; k < 8; ++k) pathE += sh_r[k];
        g_scratch[b] = freeE - pathE;
        __threadfence();
        sh_last = (atomicAdd(&g_count, 1) == B - 1) ? 1 : 0;
    }
    __syncthreads();

    // ---------------- last block: reduce all batches, write mean, reset counter ----------------
    if (sh_last) {
        float v = (tid < B) ? g_scratch[tid] : 0.f;
#pragma unroll
        for (int o = 16; o > 0; o >>= 1)
            v += __shfl_xor_sync(0xFFFFFFFFu, v, o);
        if (l == 0) sh_r[w] = v;
        __syncthreads();
        if (tid == 0) {
            float s = 0.f;
#pragma unroll
            for (int k = 0; k < 8; ++k) s += sh_r[k];
            out[0] = s * (1.f / (float)B);
            g_count = 0;                             // replay-safe reset
        }
    }
}

extern "C" void kernel_launch(void* const* d_in, const int* in_sizes, int n_in,
                              void* d_out, int out_size)
{
    const float* emis = (const float*)d_in[0];
    const int*   tags = (const int*)d_in[1];
    const float* mask = (const float*)d_in[2];
    const float* U    = (const float*)d_in[3];

    crf_main<<<B, 256>>>(emis, tags, mask, U, (float*)d_out);
}